// round 17
// baseline (speedup 1.0000x reference)
#include <cuda_runtime.h>
#include <cuda_bf16.h>
#include <math.h>

// Problem constants (fixed by setup_inputs)
#define BQ    1024
#define DIM   1024
#define CDIM  128
#define NKEYS 100000
#define KNN   5
#define EPSW  1e-6f
#define NB    2048
#define NSL   8
#define NCNT  (NB * NSL)
#define KN_LO 64.0f
#define KN_SPAN 128.0f
#define QPB   4

// ---------------- scratch (device globals; no allocations allowed) ---------
__device__ __align__(16) __nv_bfloat16 g_qh[BQ * DIM],   g_ql[BQ * DIM];
__device__ __align__(16) __nv_bfloat16 g_W1h[DIM * 512], g_W1l[DIM * 512];
__device__ __align__(16) __nv_bfloat16 g_W2h[512 * 256], g_W2l[512 * 256];
__device__ __align__(16) __nv_bfloat16 g_W3h[256 * 128], g_W3l[256 * 128];
__device__ __align__(16) __nv_bfloat16 g_D1h[128 * 256], g_D1l[128 * 256];
__device__ __align__(16) __nv_bfloat16 g_D2h[256 * 512], g_D2l[256 * 512];
__device__ __align__(16) __nv_bfloat16 g_D3h[512 * 1024], g_D3l[512 * 1024];
__device__ __align__(16) __nv_bfloat16 g_h1h[BQ * 512], g_h1l[BQ * 512];
__device__ __align__(16) __nv_bfloat16 g_h2h[BQ * 256], g_h2l[BQ * 256];
__device__ __align__(16) __nv_bfloat16 g_wh[BQ * CDIM], g_wl[BQ * CDIM];
__device__ __align__(16) __nv_bfloat16 g_g1h[BQ * 256], g_g1l[BQ * 256];
__device__ __align__(16) __nv_bfloat16 g_g2h[BQ * 512], g_g2l[BQ * 512];

__device__ float g_cq[BQ * CDIM];
__device__ float g_kn[NKEYS];
__device__ int   g_hist[NCNT];
__device__ int   g_cursor[NCNT];
__device__ int   g_scand[NKEYS];
__device__ float g_skn[NKEYS];
__device__ float g_sblo[NKEYS];

// ---------------- side stream (created once, host-side only) ----------------
static cudaStream_t g_side = nullptr;
static cudaEvent_t  g_evFork = nullptr, g_evJoin = nullptr, g_evJoin2 = nullptr;
static struct StreamInit {
    StreamInit() {
        cudaStreamCreateWithFlags(&g_side, cudaStreamNonBlocking);
        cudaEventCreateWithFlags(&g_evFork, cudaEventDisableTiming);
        cudaEventCreateWithFlags(&g_evJoin, cudaEventDisableTiming);
        cudaEventCreateWithFlags(&g_evJoin2, cudaEventDisableTiming);
    }
} g_streamInit;

// ---------------- fixed bucket mapping --------------------------------------
__device__ __forceinline__ int kn_bucket(float kn) {
    int b = (int)((kn - KN_LO) * ((float)NB / KN_SPAN));
    return min(NB - 1, max(0, b));
}
__device__ __forceinline__ float kn_floor(int b) {
    return (b == 0) ? 0.f : (KN_LO + (float)b * (KN_SPAN / (float)NB));
}

// ---------------- batched fp32 -> bf16 hi/lo split ---------------------------
struct SplitSeg { const float* src; __nv_bfloat16* h; __nv_bfloat16* l; };
struct SplitArgs { SplitSeg s[4]; int cum[5]; };

template <int NSEG, int ZERO>
__global__ void split_batch_kernel(SplitArgs a) {
    int i = blockIdx.x * blockDim.x + threadIdx.x;   // float4 units
    if (ZERO && i < NCNT) g_hist[i] = 0;
    if (i >= a.cum[NSEG]) return;
    int sg = 0;
    while (i >= a.cum[sg + 1]) sg++;
    int j = i - a.cum[sg];
    float4 v = reinterpret_cast<const float4*>(a.s[sg].src)[j];
    float x[4] = {v.x, v.y, v.z, v.w};
    unsigned short h[4], l[4];
#pragma unroll
    for (int q = 0; q < 4; q++) {
        __nv_bfloat16 hb = __float2bfloat16(x[q]);
        __nv_bfloat16 lb = __float2bfloat16(x[q] - __bfloat162float(hb));
        h[q] = __bfloat16_as_ushort(hb);
        l[q] = __bfloat16_as_ushort(lb);
    }
    uint2 hp = {(unsigned)h[0] | ((unsigned)h[1] << 16),
                (unsigned)h[2] | ((unsigned)h[3] << 16)};
    uint2 lp = {(unsigned)l[0] | ((unsigned)l[1] << 16),
                (unsigned)l[2] | ((unsigned)l[3] << 16)};
    reinterpret_cast<uint2*>(a.s[sg].h)[j] = hp;
    reinterpret_cast<uint2*>(a.s[sg].l)[j] = lp;
}

// ============================================================================
// bf16 hi/lo tensor-core GEMM (mma.sync), 4-stage cp.async pipeline,
// term-major MMA. Template on tile width: NARROW = 64x64 (warp 32x16),
// WIDE = 64x128 (warp 32x32, 1-wave grids for big-N layers).
// ============================================================================
#define GBM 64
#define GBK 64
#define ASTR 72
#define PIPE 4
// narrow (GBN=64)
#define PA_L  9216
#define PB_H  18432
#define PB_L  27648
#define PSTG  36864
#define PSM_TOTAL (PIPE * PSTG)      // 147456
// wide (GBN=128)
#define BSTRW 136
#define PB_LW 35840
#define PSTGW 53248
#define PSM_TOTALW (PIPE * PSTGW)    // 212992

__device__ __forceinline__ void mma_bf16(float c[4], const unsigned a[4],
                                         const unsigned b[2]) {
    asm volatile(
        "mma.sync.aligned.m16n8k16.row.col.f32.bf16.bf16.f32 "
        "{%0,%1,%2,%3}, {%4,%5,%6,%7}, {%8,%9}, {%0,%1,%2,%3};"
        : "+f"(c[0]), "+f"(c[1]), "+f"(c[2]), "+f"(c[3])
        : "r"(a[0]), "r"(a[1]), "r"(a[2]), "r"(a[3]), "r"(b[0]), "r"(b[1]));
}
__device__ __forceinline__ void ldmA(unsigned a[4], unsigned addr) {
    asm volatile("ldmatrix.sync.aligned.m8n8.x4.shared.b16 {%0,%1,%2,%3}, [%4];"
                 : "=r"(a[0]), "=r"(a[1]), "=r"(a[2]), "=r"(a[3]) : "r"(addr));
}
__device__ __forceinline__ void ldmB(unsigned b[2], unsigned addr) {
    asm volatile("ldmatrix.sync.aligned.m8n8.x2.trans.shared.b16 {%0,%1}, [%2];"
                 : "=r"(b[0]), "=r"(b[1]) : "r"(addr));
}
__device__ __forceinline__ void cpa16(unsigned dst, const void* src) {
    asm volatile("cp.async.cg.shared.global [%0], [%1], 16;"
                 :: "r"(dst), "l"(src));
}

// epilogue element emit (shared by both kernels)
template <int RELU, int WF32, int WBF>
__device__ __forceinline__ void emit4(float v0, float v1, float v2, float v3,
                                      int row, int col, int N,
                                      float* Cf, __nv_bfloat16* Ch,
                                      __nv_bfloat16* Cl) {
    if (RELU) {
        v0 = fmaxf(v0, 0.f); v1 = fmaxf(v1, 0.f);
        v2 = fmaxf(v2, 0.f); v3 = fmaxf(v3, 0.f);
    }
    if (WF32) {
        float2 o0 = {v0, v1}, o1 = {v2, v3};
        *reinterpret_cast<float2*>(&Cf[(size_t)row * N + col]) = o0;
        *reinterpret_cast<float2*>(&Cf[(size_t)(row + 8) * N + col]) = o1;
    }
    if (WBF) {
        __nv_bfloat16 h0 = __float2bfloat16(v0);
        __nv_bfloat16 h1 = __float2bfloat16(v1);
        __nv_bfloat16 h2 = __float2bfloat16(v2);
        __nv_bfloat16 h3 = __float2bfloat16(v3);
        unsigned hp0 = (unsigned)__bfloat16_as_ushort(h0) |
                       ((unsigned)__bfloat16_as_ushort(h1) << 16);
        unsigned hp1 = (unsigned)__bfloat16_as_ushort(h2) |
                       ((unsigned)__bfloat16_as_ushort(h3) << 16);
        unsigned lp0 = (unsigned)__bfloat16_as_ushort(
                           __float2bfloat16(v0 - __bfloat162float(h0))) |
                       ((unsigned)__bfloat16_as_ushort(
                           __float2bfloat16(v1 - __bfloat162float(h1))) << 16);
        unsigned lp1 = (unsigned)__bfloat16_as_ushort(
                           __float2bfloat16(v2 - __bfloat162float(h2))) |
                       ((unsigned)__bfloat16_as_ushort(
                           __float2bfloat16(v3 - __bfloat162float(h3))) << 16);
        *reinterpret_cast<unsigned*>(&Ch[(size_t)row * N + col]) = hp0;
        *reinterpret_cast<unsigned*>(&Ch[(size_t)(row + 8) * N + col]) = hp1;
        *reinterpret_cast<unsigned*>(&Cl[(size_t)row * N + col]) = lp0;
        *reinterpret_cast<unsigned*>(&Cl[(size_t)(row + 8) * N + col]) = lp1;
    }
}

template <int RELU, int WF32, int WBF>
__global__ __launch_bounds__(256)
void bgemm(const __nv_bfloat16* __restrict__ Ah, const __nv_bfloat16* __restrict__ Al,
           const __nv_bfloat16* __restrict__ Bh, const __nv_bfloat16* __restrict__ Bl,
           const float* __restrict__ bias,
           float* __restrict__ Cf,
           __nv_bfloat16* __restrict__ Ch, __nv_bfloat16* __restrict__ Cl,
           int M, int N, int K) {
    extern __shared__ __align__(16) char smem[];
    const unsigned sbase = (unsigned)__cvta_generic_to_shared(smem);

    const int tid  = threadIdx.x;
    const int lane = tid & 31;
    const int wid  = tid >> 5;
    const int wm   = wid & 1;
    const int wn   = wid >> 1;
    const int bm   = blockIdx.y * GBM;
    const int bn   = blockIdx.x * 64;

    const int sr  = tid >> 2;
    const int sc  = (tid & 3) << 4;
    const int a_r  = (lane & 7) + ((lane >> 3) & 1) * 8;
    const int a_k8 = (lane >> 4) * 8;
    const int b_r  = lane & 15;

    float acc[2][2][4];
#pragma unroll
    for (int mt = 0; mt < 2; mt++)
#pragma unroll
        for (int nt = 0; nt < 2; nt++)
#pragma unroll
            for (int i = 0; i < 4; i++) acc[mt][nt][i] = 0.f;

    const int ntk = K >> 6;

    auto stage = [&](int t) {
        if (t < ntk) {
            const unsigned base = sbase + (unsigned)(t & (PIPE - 1)) * PSTG;
            const int k0 = t * GBK;
            size_t ga = (size_t)(bm + sr) * K + k0 + sc;
            unsigned da = base + (sr * ASTR + sc) * 2;
            cpa16(da,             Ah + ga);
            cpa16(da + 16,        Ah + ga + 8);
            cpa16(da + PA_L,      Al + ga);
            cpa16(da + PA_L + 16, Al + ga + 8);
            size_t gb = (size_t)(k0 + sr) * N + bn + sc;
            unsigned db = base + PB_H + (sr * ASTR + sc) * 2;
            cpa16(db,                      Bh + gb);
            cpa16(db + 16,                 Bh + gb + 8);
            cpa16(db + (PB_L - PB_H),      Bl + gb);
            cpa16(db + (PB_L - PB_H) + 16, Bl + gb + 8);
        }
        asm volatile("cp.async.commit_group;");
    };

    stage(0); stage(1); stage(2);

    for (int t = 0; t < ntk; t++) {
        asm volatile("cp.async.wait_group 2;" ::: "memory");
        __syncthreads();
        stage(t + 3);

        const unsigned base = sbase + (unsigned)(t & (PIPE - 1)) * PSTG;
#pragma unroll
        for (int kk4 = 0; kk4 < 4; kk4++) {
            const int kk = kk4 * 16;
            unsigned ah[2][4], al_[2][4], bhv[2][2], blv[2][2];
#pragma unroll
            for (int mt = 0; mt < 2; mt++) {
                unsigned ro = ((wm * 32 + mt * 16 + a_r) * ASTR + kk + a_k8) * 2;
                ldmA(ah[mt],  base + ro);
                ldmA(al_[mt], base + PA_L + ro);
            }
#pragma unroll
            for (int nt = 0; nt < 2; nt++) {
                unsigned bo = ((kk + b_r) * ASTR + wn * 16 + nt * 8) * 2;
                ldmB(bhv[nt], base + PB_H + bo);
                ldmB(blv[nt], base + PB_L + bo);
            }
#pragma unroll
            for (int mt = 0; mt < 2; mt++)
#pragma unroll
                for (int nt = 0; nt < 2; nt++)
                    mma_bf16(acc[mt][nt], ah[mt], bhv[nt]);
#pragma unroll
            for (int mt = 0; mt < 2; mt++)
#pragma unroll
                for (int nt = 0; nt < 2; nt++)
                    mma_bf16(acc[mt][nt], ah[mt], blv[nt]);
#pragma unroll
            for (int mt = 0; mt < 2; mt++)
#pragma unroll
                for (int nt = 0; nt < 2; nt++)
                    mma_bf16(acc[mt][nt], al_[mt], bhv[nt]);
        }
    }

    const int g  = lane >> 2;
    const int tq = lane & 3;
#pragma unroll
    for (int mt = 0; mt < 2; mt++)
#pragma unroll
        for (int nt = 0; nt < 2; nt++) {
            int row = bm + wm * 32 + mt * 16 + g;
            int col = bn + wn * 16 + nt * 8 + tq * 2;
            float bz0 = bias[col], bz1 = bias[col + 1];
            emit4<RELU, WF32, WBF>(acc[mt][nt][0] + bz0, acc[mt][nt][1] + bz1,
                                   acc[mt][nt][2] + bz0, acc[mt][nt][3] + bz1,
                                   row, col, N, Cf, Ch, Cl);
        }
}

// wide variant: GBN=128, warp tile 32x32 (2x m16, 4x n8)
template <int RELU, int WF32, int WBF>
__global__ __launch_bounds__(256)
void bgemmw(const __nv_bfloat16* __restrict__ Ah, const __nv_bfloat16* __restrict__ Al,
            const __nv_bfloat16* __restrict__ Bh, const __nv_bfloat16* __restrict__ Bl,
            const float* __restrict__ bias,
            float* __restrict__ Cf,
            __nv_bfloat16* __restrict__ Ch, __nv_bfloat16* __restrict__ Cl,
            int M, int N, int K) {
    extern __shared__ __align__(16) char smem[];
    const unsigned sbase = (unsigned)__cvta_generic_to_shared(smem);

    const int tid  = threadIdx.x;
    const int lane = tid & 31;
    const int wid  = tid >> 5;
    const int wm   = wid & 1;       // 2 warps along M (32 rows)
    const int wn   = wid >> 1;      // 4 warps along N (32 cols)
    const int bm   = blockIdx.y * GBM;
    const int bn   = blockIdx.x * 128;

    const int sr  = tid >> 2;           // 0..63
    const int sc  = (tid & 3) << 4;     // A: 0,16,32,48
    const int bcc = (tid & 3) << 5;     // B: 0,32,64,96
    const int a_r  = (lane & 7) + ((lane >> 3) & 1) * 8;
    const int a_k8 = (lane >> 4) * 8;
    const int b_r  = lane & 15;

    float acc[2][4][4];
#pragma unroll
    for (int mt = 0; mt < 2; mt++)
#pragma unroll
        for (int nt = 0; nt < 4; nt++)
#pragma unroll
            for (int i = 0; i < 4; i++) acc[mt][nt][i] = 0.f;

    const int ntk = K >> 6;

    auto stage = [&](int t) {
        if (t < ntk) {
            const unsigned base = sbase + (unsigned)(t & (PIPE - 1)) * PSTGW;
            const int k0 = t * GBK;
            size_t ga = (size_t)(bm + sr) * K + k0 + sc;
            unsigned da = base + (sr * ASTR + sc) * 2;
            cpa16(da,             Ah + ga);
            cpa16(da + 16,        Ah + ga + 8);
            cpa16(da + PA_L,      Al + ga);
            cpa16(da + PA_L + 16, Al + ga + 8);
            size_t gb = (size_t)(k0 + sr) * N + bn + bcc;
            unsigned db = base + PB_H + (sr * BSTRW + bcc) * 2;
#pragma unroll
            for (int c = 0; c < 4; c++) {
                cpa16(db + c * 16,                  Bh + gb + c * 8);
                cpa16(db + (PB_LW - PB_H) + c * 16, Bl + gb + c * 8);
            }
        }
        asm volatile("cp.async.commit_group;");
    };

    stage(0); stage(1); stage(2);

    for (int t = 0; t < ntk; t++) {
        asm volatile("cp.async.wait_group 2;" ::: "memory");
        __syncthreads();
        stage(t + 3);

        const unsigned base = sbase + (unsigned)(t & (PIPE - 1)) * PSTGW;
#pragma unroll
        for (int kk4 = 0; kk4 < 4; kk4++) {
            const int kk = kk4 * 16;
            unsigned ah[2][4], al_[2][4], bhv[4][2], blv[4][2];
#pragma unroll
            for (int mt = 0; mt < 2; mt++) {
                unsigned ro = ((wm * 32 + mt * 16 + a_r) * ASTR + kk + a_k8) * 2;
                ldmA(ah[mt],  base + ro);
                ldmA(al_[mt], base + PA_L + ro);
            }
#pragma unroll
            for (int nt = 0; nt < 4; nt++) {
                unsigned bo = ((kk + b_r) * BSTRW + wn * 32 + nt * 8) * 2;
                ldmB(bhv[nt], base + PB_H + bo);
                ldmB(blv[nt], base + PB_LW + bo);
            }
#pragma unroll
            for (int mt = 0; mt < 2; mt++)
#pragma unroll
                for (int nt = 0; nt < 4; nt++)
                    mma_bf16(acc[mt][nt], ah[mt], bhv[nt]);
#pragma unroll
            for (int mt = 0; mt < 2; mt++)
#pragma unroll
                for (int nt = 0; nt < 4; nt++)
                    mma_bf16(acc[mt][nt], ah[mt], blv[nt]);
#pragma unroll
            for (int mt = 0; mt < 2; mt++)
#pragma unroll
                for (int nt = 0; nt < 4; nt++)
                    mma_bf16(acc[mt][nt], al_[mt], bhv[nt]);
        }
    }

    const int g  = lane >> 2;
    const int tq = lane & 3;
#pragma unroll
    for (int mt = 0; mt < 2; mt++)
#pragma unroll
        for (int nt = 0; nt < 4; nt++) {
            int row = bm + wm * 32 + mt * 16 + g;
            int col = bn + wn * 32 + nt * 8 + tq * 2;
            float bz0 = bias[col], bz1 = bias[col + 1];
            emit4<RELU, WF32, WBF>(acc[mt][nt][0] + bz0, acc[mt][nt][1] + bz1,
                                   acc[mt][nt][2] + bz0, acc[mt][nt][3] + bz1,
                                   row, col, N, Cf, Ch, Cl);
        }
}

// ---------------- key norms + sliced histogram -------------------------------
__global__ void rownorm_kernel(const float* __restrict__ X,
                               float* __restrict__ out, int rows) {
    int gw = (int)((blockIdx.x * (size_t)blockDim.x + threadIdx.x) >> 5);
    int lane = threadIdx.x & 31;
    if (gw >= rows) return;
    float4 v = reinterpret_cast<const float4*>(X + (size_t)gw * 128)[lane];
    float s = v.x * v.x + v.y * v.y + v.z * v.z + v.w * v.w;
#pragma unroll
    for (int o = 16; o; o >>= 1) s += __shfl_xor_sync(0xffffffffu, s, o);
    if (lane == 0) {
        out[gw] = s;
        atomicAdd(&g_hist[kn_bucket(s) * NSL + (gw & (NSL - 1))], 1);
    }
}

// ---------------- exclusive scan over NCNT counters --------------------------
__global__ void scan_kernel() {
    __shared__ int wsum[32];
    const int t = threadIdx.x;
    const int lane = t & 31, w = t >> 5;
    const int base = t * 16;
    int loc[16];
    int s = 0;
#pragma unroll
    for (int i = 0; i < 16; i++) { loc[i] = g_hist[base + i]; s += loc[i]; }
    int x = s;
#pragma unroll
    for (int o = 1; o < 32; o <<= 1) {
        int y = __shfl_up_sync(0xffffffffu, x, o);
        if (lane >= o) x += y;
    }
    if (lane == 31) wsum[w] = x;
    __syncthreads();
    if (w == 0) {
        int v = wsum[lane];
#pragma unroll
        for (int o = 1; o < 32; o <<= 1) {
            int y = __shfl_up_sync(0xffffffffu, v, o);
            if (lane >= o) v += y;
        }
        wsum[lane] = v;
    }
    __syncthreads();
    int excl = x - s + (w > 0 ? wsum[w - 1] : 0);
#pragma unroll
    for (int i = 0; i < 16; i++) { g_cursor[base + i] = excl; excl += loc[i]; }
}

__global__ void scatter_kernel() {
    int n = blockIdx.x * blockDim.x + threadIdx.x;
    if (n >= NKEYS) return;
    float kn = g_kn[n];
    int b = kn_bucket(kn);
    int pos = atomicAdd(&g_cursor[b * NSL + (n & (NSL - 1))], 1);
    g_scand[pos] = n;
    g_skn[pos]   = kn;
    g_sblo[pos]  = kn_floor(b);
}

// ---------------- exact rescore: 4 queries/block, warp-per-query ------------
__global__ __launch_bounds__(128, 8)
void rescore_kernel(const float* __restrict__ keys,
                    const float* __restrict__ values,
                    float* __restrict__ conf_out) {
    const int tid  = threadIdx.x;
    const int lane = tid & 31;
    const int w    = tid >> 5;
    const int q    = blockIdx.x * QPB + w;
    __shared__ float sq[QPB][CDIM];
    __shared__ float rd[QPB][KNN];
    __shared__ int   ri[QPB][KNN];
    __shared__ float sw_[QPB][KNN];
    __shared__ int   done[QPB];

    float4 qv4 = reinterpret_cast<const float4*>(g_cq + (size_t)q * CDIM)[lane];
    *reinterpret_cast<float4*>(&sq[w][lane * 4]) = qv4;
    float s = qv4.x * qv4.x + qv4.y * qv4.y + qv4.z * qv4.z + qv4.w * qv4.w;
#pragma unroll
    for (int o = 16; o; o >>= 1) s += __shfl_xor_sync(0xffffffffu, s, o);
    const float qn = s;
    const float qb = sqrtf(qn);

    if (lane < KNN) { rd[w][lane] = 3.4e38f; ri[w][lane] = 0x7fffffff; }
    if (lane == 0) done[w] = 0;
    __syncthreads();

    const float4* sq4 = reinterpret_cast<const float4*>(sq[w]);

    for (int c0 = 0; c0 < NKEYS; c0 += 32) {
        if (lane == 0 && !done[w] && c0 > 0) {
            float blo = g_sblo[c0];
            float lb = qn + blo - 2.f * qb * sqrtf(blo) - 1e-3f;
            if (lb > rd[w][KNN - 1]) done[w] = 1;
        }
        __syncthreads();
        if (done[0] && done[1] && done[2] && done[3]) break;

        if (!done[w]) {
            int j = c0 + lane;
            float d = 3.4e38f;
            int nidx = 0x7fffffff;
            if (j < NKEYS) {
                int n = g_scand[j];
                const float4* kr =
                    reinterpret_cast<const float4*>(keys + (size_t)n * CDIM);
                float a0 = 0.f, a1 = 0.f, a2 = 0.f, a3 = 0.f;
#pragma unroll
                for (int dd = 0; dd < CDIM / 4; dd++) {
                    float4 kv = __ldg(&kr[dd]);
                    float4 qv = sq4[dd];
                    a0 = fmaf(qv.x, kv.x, a0);
                    a1 = fmaf(qv.y, kv.y, a1);
                    a2 = fmaf(qv.z, kv.z, a2);
                    a3 = fmaf(qv.w, kv.w, a3);
                }
                float dot = (a0 + a1) + (a2 + a3);
                d = qn + g_skn[j] - 2.f * dot;
                nidx = n;
            }
            float rd4 = rd[w][KNN - 1];
            int   ri4 = ri[w][KNN - 1];
#pragma unroll
            for (int r = 0; r < KNN; r++) {
                float v = d; int ix = nidx;
#pragma unroll
                for (int o = 16; o; o >>= 1) {
                    float v2 = __shfl_xor_sync(0xffffffffu, v, o);
                    int   i2 = __shfl_xor_sync(0xffffffffu, ix, o);
                    if (v2 < v || (v2 == v && i2 < ix)) { v = v2; ix = i2; }
                }
                if (!(v < rd4 || (v == rd4 && ix < ri4))) break;
                if (lane == 0) {
                    int p = KNN - 1;
                    while (p > 0 && (rd[w][p - 1] > v ||
                                     (rd[w][p - 1] == v && ri[w][p - 1] > ix))) {
                        rd[w][p] = rd[w][p - 1]; ri[w][p] = ri[w][p - 1]; p--;
                    }
                    rd[w][p] = v; ri[w][p] = ix;
                }
                if (d == v && nidx == ix) { d = 3.4e38f; nidx = 0x7fffffff; }
                __syncwarp();
                rd4 = rd[w][KNN - 1];
                ri4 = ri[w][KNN - 1];
            }
        }
        __syncthreads();
    }

    if (lane == 0) {
        float ww[KNN], ws = 0.f;
#pragma unroll
        for (int j2 = 0; j2 < KNN; j2++) { ww[j2] = 1.f / (rd[w][j2] + EPSW); ws += ww[j2]; }
#pragma unroll
        for (int j2 = 0; j2 < KNN; j2++) sw_[w][j2] = ww[j2] / ws;
        conf_out[q] = 1.f / (rd[w][0] + EPSW);
    }
    __syncwarp();

#pragma unroll
    for (int dd = 0; dd < 4; dd++) {
        int dcol = dd * 32 + lane;
        float acc = 0.f;
#pragma unroll
        for (int j2 = 0; j2 < KNN; j2++)
            acc += sw_[w][j2] * values[(size_t)ri[w][j2] * CDIM + dcol];
        __nv_bfloat16 hb = __float2bfloat16(acc);
        g_wh[(size_t)q * CDIM + dcol] = hb;
        g_wl[(size_t)q * CDIM + dcol] =
            __float2bfloat16(acc - __bfloat162float(hb));
    }
}

// ---------------- launch ----------------------------------------------------
extern "C" void kernel_launch(void* const* d_in, const int* in_sizes, int n_in,
                              void* d_out, int out_size) {
    const float* query = (const float*)d_in[0];
    const float* W1    = (const float*)d_in[1];
    const float* b1    = (const float*)d_in[2];
    const float* W2    = (const float*)d_in[3];
    const float* b2    = (const float*)d_in[4];
    const float* W3    = (const float*)d_in[5];
    const float* b3    = (const float*)d_in[6];
    const float* keys  = (const float*)d_in[7];
    const float* values= (const float*)d_in[8];
    const float* D1w   = (const float*)d_in[9];
    const float* D1b   = (const float*)d_in[10];
    const float* D2w   = (const float*)d_in[11];
    const float* D2b   = (const float*)d_in[12];
    const float* D3w   = (const float*)d_in[13];
    const float* D3b   = (const float*)d_in[14];

    float* out  = (float*)d_out;
    float* conf = out + (size_t)BQ * DIM;

    void *qh, *ql, *W1h, *W1l, *W2h, *W2l, *W3h, *W3l;
    void *D1h, *D1l, *D2h, *D2l, *D3h, *D3l;
    void *h1h, *h1l, *h2h, *h2l, *wh, *wl, *g1h, *g1l, *g2h, *g2l;
    void *cq, *kn;
    cudaGetSymbolAddress(&qh, g_qh);   cudaGetSymbolAddress(&ql, g_ql);
    cudaGetSymbolAddress(&W1h, g_W1h); cudaGetSymbolAddress(&W1l, g_W1l);
    cudaGetSymbolAddress(&W2h, g_W2h); cudaGetSymbolAddress(&W2l, g_W2l);
    cudaGetSymbolAddress(&W3h, g_W3h); cudaGetSymbolAddress(&W3l, g_W3l);
    cudaGetSymbolAddress(&D1h, g_D1h); cudaGetSymbolAddress(&D1l, g_D1l);
    cudaGetSymbolAddress(&D2h, g_D2h); cudaGetSymbolAddress(&D2l, g_D2l);
    cudaGetSymbolAddress(&D3h, g_D3h); cudaGetSymbolAddress(&D3l, g_D3l);
    cudaGetSymbolAddress(&h1h, g_h1h); cudaGetSymbolAddress(&h1l, g_h1l);
    cudaGetSymbolAddress(&h2h, g_h2h); cudaGetSymbolAddress(&h2l, g_h2l);
    cudaGetSymbolAddress(&wh, g_wh);   cudaGetSymbolAddress(&wl, g_wl);
    cudaGetSymbolAddress(&g1h, g_g1h); cudaGetSymbolAddress(&g1l, g_g1l);
    cudaGetSymbolAddress(&g2h, g_g2h); cudaGetSymbolAddress(&g2l, g_g2l);
    cudaGetSymbolAddress(&cq, g_cq);
    cudaGetSymbolAddress(&kn, g_kn);

    cudaFuncSetAttribute(bgemm<1, 0, 1>,
                         cudaFuncAttributeMaxDynamicSharedMemorySize, PSM_TOTAL);
    cudaFuncSetAttribute(bgemm<0, 1, 0>,
                         cudaFuncAttributeMaxDynamicSharedMemorySize, PSM_TOTAL);
    cudaFuncSetAttribute(bgemmw<0, 1, 0>,
                         cudaFuncAttributeMaxDynamicSharedMemorySize, PSM_TOTALW);

    // 1. main split: query + encode weights (+ counter zeroing)
    SplitArgs se;
    {
        int sz[4] = {BQ * DIM / 4, DIM * 512 / 4, 512 * 256 / 4, 256 * 128 / 4};
        const float* sr[4] = {query, W1, W2, W3};
        void* hh[4] = {qh, W1h, W2h, W3h};
        void* lL[4] = {ql, W1l, W2l, W3l};
        se.cum[0] = 0;
        for (int i = 0; i < 4; i++) {
            se.s[i].src = sr[i];
            se.s[i].h = (__nv_bfloat16*)hh[i];
            se.s[i].l = (__nv_bfloat16*)lL[i];
            se.cum[i + 1] = se.cum[i] + sz[i];
        }
    }
    split_batch_kernel<4, 1><<<(se.cum[4] + 255) / 256, 256>>>(se);

    // fork: retrieval prep + decode-weight split on side stream
    cudaEventRecord(g_evFork, 0);
    cudaStreamWaitEvent(g_side, g_evFork, 0);
    rownorm_kernel<<<(NKEYS * 32 + 255) / 256, 256, 0, g_side>>>(
        keys, (float*)kn, NKEYS);
    scan_kernel<<<1, 1024, 0, g_side>>>();
    scatter_kernel<<<(NKEYS + 255) / 256, 256, 0, g_side>>>();
    cudaEventRecord(g_evJoin, g_side);

    SplitArgs sd;
    {
        int sz[3] = {128 * 256 / 4, 256 * 512 / 4, 512 * 1024 / 4};
        const float* sr[3] = {D1w, D2w, D3w};
        void* hh[3] = {D1h, D2h, D3h};
        void* lL[3] = {D1l, D2l, D3l};
        sd.cum[0] = 0;
        for (int i = 0; i < 3; i++) {
            sd.s[i].src = sr[i];
            sd.s[i].h = (__nv_bfloat16*)hh[i];
            sd.s[i].l = (__nv_bfloat16*)lL[i];
            sd.cum[i + 1] = sd.cum[i] + sz[i];
        }
        sd.s[3] = sd.s[2]; sd.cum[4] = sd.cum[3];
    }
    split_batch_kernel<3, 0><<<(sd.cum[3] + 255) / 256, 256, 0, g_side>>>(sd);
    cudaEventRecord(g_evJoin2, g_side);

    // Encode MLP (main stream)
    bgemm<1, 0, 1><<<dim3(512 / 64, BQ / GBM), 256, PSM_TOTAL>>>(
        (__nv_bfloat16*)qh, (__nv_bfloat16*)ql, (__nv_bfloat16*)W1h, (__nv_bfloat16*)W1l,
        b1, nullptr, (__nv_bfloat16*)h1h, (__nv_bfloat16*)h1l, BQ, 512, 1024);
    bgemm<1, 0, 1><<<dim3(256 / 64, BQ / GBM), 256, PSM_TOTAL>>>(
        (__nv_bfloat16*)h1h, (__nv_bfloat16*)h1l, (__nv_bfloat16*)W2h, (__nv_bfloat16*)W2l,
        b2, nullptr, (__nv_bfloat16*)h2h, (__nv_bfloat16*)h2l, BQ, 256, 512);
    bgemm<0, 1, 0><<<dim3(128 / 64, BQ / GBM), 256, PSM_TOTAL>>>(
        (__nv_bfloat16*)h2h, (__nv_bfloat16*)h2l, (__nv_bfloat16*)W3h, (__nv_bfloat16*)W3l,
        b3, (float*)cq, nullptr, nullptr, BQ, 128, 256);

    // join 1: rescore needs scatter
    cudaStreamWaitEvent(0, g_evJoin, 0);
    rescore_kernel<<<BQ / QPB, 128>>>(keys, values, conf);

    // join 2: decode needs split decode weights
    cudaStreamWaitEvent(0, g_evJoin2, 0);

    // Decode MLP
    bgemm<1, 0, 1><<<dim3(256 / 64, BQ / GBM), 256, PSM_TOTAL>>>(
        (__nv_bfloat16*)wh, (__nv_bfloat16*)wl, (__nv_bfloat16*)D1h, (__nv_bfloat16*)D1l,
        D1b, nullptr, (__nv_bfloat16*)g1h, (__nv_bfloat16*)g1l, BQ, 256, 128);
    bgemm<1, 0, 1><<<dim3(512 / 64, BQ / GBM), 256, PSM_TOTAL>>>(
        (__nv_bfloat16*)g1h, (__nv_bfloat16*)g1l, (__nv_bfloat16*)D2h, (__nv_bfloat16*)D2l,
        D2b, nullptr, (__nv_bfloat16*)g2h, (__nv_bfloat16*)g2l, BQ, 512, 256);
    bgemmw<0, 1, 0><<<dim3(1024 / 128, BQ / GBM), 256, PSM_TOTALW>>>(
        (__nv_bfloat16*)g2h, (__nv_bfloat16*)g2l, (__nv_bfloat16*)D3h, (__nv_bfloat16*)D3l,
        D3b, out, nullptr, nullptr, BQ, 1024, 512);
}